// round 7
// baseline (speedup 1.0000x reference)
#include <cuda_runtime.h>
#include <cuda_bf16.h>
#include <cstdint>
#include <cstddef>

// ---------------------------------------------------------------------------
// Pipeline:
//   inputs (4,3,512,512) f32
//   conv1 3->64 @512² (FFMA), BN1 folded into conv2 loader
//   conv2 64->64 @512²  -- mma.sync bf16 3-term implicit GEMM, stats in epilogue
//   BN2+ReLU -> skip_con (output 2), fused with Haar DWT
//   conv3 256->64 @256² -- mma.sync bf16 3-term implicit GEMM, stats in epilogue
//   BN3+ReLU -> dwt_out (output 1)
//   d_out layout: [dwt_out 16,777,216 f32][skip_con 67,108,864 f32]
// PTX target is compute_100 (no tcgen05) -> sm_80-class mma.sync/ldmatrix/cp.async.
// ---------------------------------------------------------------------------

#define DWT_ELEMS  16777216ull
#define SKIP_ELEMS 67108864ull

__device__ float g_bufA[67108864];
__device__ float g_bufB[67108864];
__device__ float g_wT[256 * 576];              // conv1 FFMA weights [c][oc*9+j]
__device__ __nv_bfloat16 g_wB[331776];         // mma weights [tt][term][oc][72]

__device__ double g_sum[3][64];
__device__ double g_sq [3][64];
__device__ float  g_nsc[3][64];
__device__ float  g_nsh[3][64];

// ============================ helpers ======================================
__device__ __forceinline__ uint32_t smem_u32(const void* p) {
    uint32_t a;
    asm("{ .reg .u64 t; cvta.to.shared.u64 t, %1; cvt.u32.u64 %0, t; }" : "=r"(a) : "l"(p));
    return a;
}
__device__ __forceinline__ void ldmatrix4(uint32_t* r, uint32_t addr) {
    asm volatile("ldmatrix.sync.aligned.m8n8.x4.shared.b16 {%0,%1,%2,%3}, [%4];"
                 : "=r"(r[0]), "=r"(r[1]), "=r"(r[2]), "=r"(r[3]) : "r"(addr));
}
__device__ __forceinline__ void mma_bf16(float* c, const uint32_t* a, const uint32_t* b) {
    asm volatile(
        "mma.sync.aligned.m16n8k16.row.col.f32.bf16.bf16.f32 "
        "{%0,%1,%2,%3}, {%4,%5,%6,%7}, {%8,%9}, {%0,%1,%2,%3};"
        : "+f"(c[0]), "+f"(c[1]), "+f"(c[2]), "+f"(c[3])
        : "r"(a[0]), "r"(a[1]), "r"(a[2]), "r"(a[3]), "r"(b[0]), "r"(b[1]));
}
__device__ __forceinline__ void cp_async16(uint32_t smem_addr, const void* gptr) {
    asm volatile("cp.async.cg.shared.global [%0], [%1], 16;"
                 :: "r"(smem_addr), "l"(gptr) : "memory");
}
__device__ __forceinline__ void cp_commit() {
    asm volatile("cp.async.commit_group;" ::: "memory");
}
__device__ __forceinline__ void cp_wait_all() {
    asm volatile("cp.async.wait_group 0;" ::: "memory");
}

// ============================ small kernels ================================
__global__ void zero_stats_kernel() {
    int i = threadIdx.x;
    if (i < 192) { ((double*)g_sum)[i] = 0.0; ((double*)g_sq)[i] = 0.0; }
}

__global__ void finalize_stats_kernel(int stage, const float* __restrict__ gamma,
                                      const float* __restrict__ beta, double inv_cnt) {
    int c = threadIdx.x;
    if (c < 64) {
        double m   = g_sum[stage][c] * inv_cnt;
        double var = g_sq [stage][c] * inv_cnt - m * m;
        double sc  = (double)gamma[c] / sqrt(var + 1e-5);
        g_nsc[stage][c] = (float)sc;
        g_nsh[stage][c] = (float)((double)beta[c] - m * sc);
    }
}

// conv1 FFMA weight reformat: w[oc][c][3][3] -> wT[c][oc*9+j]
__global__ void transpose_w_kernel(const float* __restrict__ w, float* __restrict__ wT, int C) {
    int i = blockIdx.x * blockDim.x + threadIdx.x;
    if (i < C * 576) {
        int c = i / 576, r = i % 576;
        wT[i] = w[((size_t)(r / 9) * C + c) * 9 + (r % 9)];
    }
}

// mma weight prep: w[oc][C][9] -> wB[tt=slab*9+tap][term hi/lo][oc][72ch] bf16
__global__ void prep_wmma_kernel(const float* __restrict__ w,
                                 __nv_bfloat16* __restrict__ wB, int C) {
    int i = blockIdx.x * blockDim.x + threadIdx.x;
    int nSlabs = C >> 6;
    int total = nSlabs * 9 * 2 * 64 * 72;
    if (i >= total) return;
    int ch   = i % 72;
    int oc   = (i / 72) % 64;
    int term = (i / (72 * 64)) % 2;
    int tt   = i / (72 * 64 * 2);
    int slab = tt / 9, tap = tt % 9;
    float v = 0.0f;
    if (ch < 64) v = w[((size_t)oc * C + slab * 64 + ch) * 9 + tap];
    __nv_bfloat16 h = __float2bfloat16(v);
    wB[i] = (term == 0) ? h : __float2bfloat16(v - __bfloat162float(h));
}

// ================= conv1: direct FFMA 3x3 (known-good, C=3) =================
template<bool NORM>
__global__ __launch_bounds__(512)
void conv3x3_kernel(const float* __restrict__ in, const float* __restrict__ wT,
                    const float* __restrict__ bias, float* __restrict__ out,
                    int C, int H, int W, int nstage, int ostage)
{
    __shared__ float sIn[2][10 * 34];
    __shared__ float sW [2][576];
    const int tid = threadIdx.x, col = tid & 31, g = tid >> 5, oc0 = g * 4;
    const int col0 = blockIdx.x * 32, row0 = blockIdx.y * 8, n = blockIdx.z;
    const int lr = tid / 34, lc = tid % 34;
    const int gr = row0 - 1 + lr, gc = col0 - 1 + lc;
    const bool ldin = (tid < 340) && gr >= 0 && gr < H && gc >= 0 && gc < W;
    const bool pat = (tid < 340);
    const size_t in_off = ((size_t)n * C * H + (size_t)gr) * W + gc;
    const bool ldw2 = (tid < 64);

    float acc[4][8];
    #pragma unroll
    for (int ko = 0; ko < 4; ko++) {
        float b = bias[oc0 + ko];
        #pragma unroll
        for (int rr = 0; rr < 8; rr++) acc[ko][rr] = b;
    }
    {
        float v = 0.0f;
        if (ldin) { v = in[in_off]; if (NORM) v = fmaf(v, g_nsc[nstage][0], g_nsh[nstage][0]); }
        if (pat) sIn[0][tid] = v;
        sW[0][tid] = (tid < 576) ? wT[tid] : 0.0f;
        if (ldw2) sW[0][tid + 512] = wT[tid + 512];
    }
    __syncthreads();
    int b = 0;
    for (int c = 0; c < C; c++) {
        float nv = 0.0f, nw0 = 0.0f, nw1 = 0.0f;
        const bool more = (c + 1 < C);
        if (more) {
            if (ldin) {
                nv = in[in_off + (size_t)(c + 1) * H * W];
                if (NORM) nv = fmaf(nv, g_nsc[nstage][c + 1], g_nsh[nstage][c + 1]);
            }
            const float* wrow = wT + (size_t)(c + 1) * 576;
            if (tid < 576) nw0 = wrow[tid];
            if (ldw2)      nw1 = wrow[tid + 512];
        }
        float v[10][3];
        #pragma unroll
        for (int r = 0; r < 10; r++)
            #pragma unroll
            for (int dj = 0; dj < 3; dj++) v[r][dj] = sIn[b][r * 34 + col + dj];
        #pragma unroll
        for (int ko = 0; ko < 4; ko++) {
            float w[9];
            #pragma unroll
            for (int j = 0; j < 9; j++) w[j] = sW[b][(oc0 + ko) * 9 + j];
            #pragma unroll
            for (int rr = 0; rr < 8; rr++) {
                float s = acc[ko][rr];
                #pragma unroll
                for (int di = 0; di < 3; di++)
                    #pragma unroll
                    for (int dj = 0; dj < 3; dj++)
                        s = fmaf(w[di * 3 + dj], v[rr + di][dj], s);
                acc[ko][rr] = s;
            }
        }
        if (more) {
            if (pat) sIn[b ^ 1][tid] = nv;
            if (tid < 576) sW[b ^ 1][tid] = nw0;
            if (ldw2)      sW[b ^ 1][tid + 512] = nw1;
        }
        __syncthreads();
        b ^= 1;
    }
    #pragma unroll
    for (int ko = 0; ko < 4; ko++) {
        float s = 0.0f, q = 0.0f;
        #pragma unroll
        for (int rr = 0; rr < 8; rr++) {
            float x = acc[ko][rr];
            out[((size_t)(n * 64 + oc0 + ko) * H + row0 + rr) * W + col0 + col] = x;
            s += x; q = fmaf(x, x, q);
        }
        #pragma unroll
        for (int off = 16; off; off >>= 1) {
            s += __shfl_down_sync(0xffffffffu, s, off);
            q += __shfl_down_sync(0xffffffffu, q, off);
        }
        if (col == 0) {
            atomicAdd(&g_sum[ostage][oc0 + ko], (double)s);
            atomicAdd(&g_sq [ostage][oc0 + ko], (double)q);
        }
    }
}

// ============ conv2/conv3: mma.sync bf16 implicit GEMM v2 ==================
// Block 256 thr (8 warps = 4m x 2n). Output tile 256 pixels (8 rows x 32 cols)
// x 64 oc. Warp tile 64m x 32n (acc 4x4x4). Patch 10x34 per channel, bf16
// hi/lo, 72-ch pad (144B rows). Taps via ldmatrix address shift.
// 3-term split: Ah*Bh + Ah*Bl + Al*Bh. B tiles cp.async double-buffered.
// Epilogue: smem C staging (stride 257, conflict-free), coalesced store,
// per-oc BN stats with one double atomicAdd per oc per block.
// SMEM: [0]       A_hi patch 340x144B (48,960)   } reused as f32 C staging
//       [48960]   A_lo patch          (48,960)   }  (64x257x4 = 65,792)
//       [97920]   B double buffer: 2 x 18,432
//       [134784]  bias f32[64]
#define MM_SA_H   0
#define MM_SA_L   48960
#define MM_SB     97920
#define MM_SBIAS  134784
#define MM_SMEM   135168

template<bool NORM>
__global__ __launch_bounds__(256, 1)
void conv_mma_kernel(const float* __restrict__ in, const __nv_bfloat16* __restrict__ wB,
                     const float* __restrict__ bias, float* __restrict__ out,
                     int C, int H, int W, int nstage, int ostage)
{
    extern __shared__ char smem[];
    const uint32_t sb = smem_u32(smem);
    const int tid = threadIdx.x, wid = tid >> 5, lane = tid & 31;
    const int wm = wid & 3, wn = wid >> 2;
    const int bcol = blockIdx.x * 32, brow = blockIdx.y * 8, n = blockIdx.z;
    const size_t HW = (size_t)H * W;
    const int nSlabs = C >> 6, TT = nSlabs * 9;
    float* sBias = (float*)(smem + MM_SBIAS);
    if (tid < 64) sBias[tid] = bias[tid];

    // per-lane A (ldmatrix) base addrs per m-tile: lanes 0-15 rows, 16-31 +16B
    const int ml = lane & 15;
    const uint32_t koff = (lane >= 16) ? 16u : 0u;
    uint32_t ap[4];
    #pragma unroll
    for (int mt = 0; mt < 4; mt++) {
        int m = wm * 64 + mt * 16 + ml;
        int pr = m >> 5, pc = m & 31;
        ap[mt] = (uint32_t)((pr * 34 + pc) * 144) + koff;
    }
    // per-lane B base: n-row = lane>>2, k-quad = lane&3 -> conflict-free
    const uint32_t bBrel = (uint32_t)((wn * 32 + (lane >> 2)) * 144 + (lane & 3) * 4);

    float acc[4][4][4];
    #pragma unroll
    for (int mt = 0; mt < 4; mt++)
        #pragma unroll
        for (int nt = 0; nt < 4; nt++)
            #pragma unroll
            for (int k = 0; k < 4; k++) acc[mt][nt][k] = 0.0f;

    // initial B tile (tt=0) -> buf 0 via cp.async (overlaps patch build)
    #pragma unroll
    for (int i = 0; i < 5; i++) {
        int j = tid + i * 256;
        if (j < 1152) cp_async16(sb + MM_SB + j * 16, (const char*)wB + j * 16);
    }
    cp_commit();

    int buf = 0;
    for (int slab = 0; slab < nSlabs; slab++) {
        // ---- patch: 64ch x 10x34, f32 -> bf16 hi/lo, BN folded, zero pad ----
        const float* inBase = in + (size_t)(n * C + slab * 64) * HW;
        for (int i = tid; i < 64 * 340; i += 256) {
            int c = i / 340, p = i % 340;
            int r = p / 34, cc = p % 34;
            int gr = brow - 1 + r, gc = bcol - 1 + cc;
            float v = 0.0f;
            if (gr >= 0 && gr < H && gc >= 0 && gc < W) {
                v = inBase[(size_t)c * HW + (size_t)gr * W + gc];
                if (NORM) v = fmaf(v, g_nsc[nstage][slab * 64 + c], g_nsh[nstage][slab * 64 + c]);
            }
            __nv_bfloat16 h = __float2bfloat16(v);
            __nv_bfloat16 l = __float2bfloat16(v - __bfloat162float(h));
            *(__nv_bfloat16*)(smem + MM_SA_H + p * 144 + c * 2) = h;
            *(__nv_bfloat16*)(smem + MM_SA_L + p * 144 + c * 2) = l;
        }
        cp_wait_all();
        __syncthreads();

        for (int tap = 0; tap < 9; tap++) {
            const int tt = slab * 9 + tap;
            // prefetch next B tile into other buffer (overlaps mma below)
            if (tt + 1 < TT) {
                const char* src = (const char*)wB + (size_t)(tt + 1) * 18432;
                uint32_t dst = sb + MM_SB + (buf ^ 1) * 18432;
                #pragma unroll
                for (int i = 0; i < 5; i++) {
                    int j = tid + i * 256;
                    if (j < 1152) cp_async16(dst + j * 16, src + j * 16);
                }
            }
            cp_commit();

            const int di = tap / 3, dj = tap % 3;
            const uint32_t toff = (uint32_t)((di * 34 + dj) * 144);
            const uint32_t bBase = sb + MM_SB + (uint32_t)buf * 18432 + bBrel;

            #pragma unroll
            for (int ks = 0; ks < 4; ks++) {
                uint32_t ah[4][4], al[4][4];
                #pragma unroll
                for (int mt = 0; mt < 4; mt++)
                    ldmatrix4(ah[mt], sb + MM_SA_H + ap[mt] + toff + ks * 32);
                #pragma unroll
                for (int mt = 0; mt < 4; mt++)
                    ldmatrix4(al[mt], sb + MM_SA_L + ap[mt] + toff + ks * 32);
                uint32_t bh[4][2], bl[4][2];
                #pragma unroll
                for (int nt = 0; nt < 4; nt++) {
                    const char* sp = smem + (bBase - sb) + (uint32_t)(nt * 1152 + ks * 32);
                    bh[nt][0] = *(const uint32_t*)(sp);
                    bh[nt][1] = *(const uint32_t*)(sp + 16);
                    bl[nt][0] = *(const uint32_t*)(sp + 9216);
                    bl[nt][1] = *(const uint32_t*)(sp + 9216 + 16);
                }
                #pragma unroll
                for (int mt = 0; mt < 4; mt++)
                    #pragma unroll
                    for (int nt = 0; nt < 4; nt++) {
                        mma_bf16(acc[mt][nt], ah[mt], bh[nt]);
                        mma_bf16(acc[mt][nt], ah[mt], bl[nt]);
                        mma_bf16(acc[mt][nt], al[mt], bh[nt]);
                    }
            }

            cp_wait_all();
            __syncthreads();
            buf ^= 1;
        }
    }

    // ---- epilogue: stage C (stride 257) with bias, store, BN stats ----
    float* sC = (float*)smem;          // sC[oc*257 + m], 65,792 B
    const int l4 = lane >> 2, l2 = (lane & 3) * 2;
    #pragma unroll
    for (int mt = 0; mt < 4; mt++)
        #pragma unroll
        for (int nt = 0; nt < 4; nt++) {
            int row = wm * 64 + mt * 16 + l4;
            int col = wn * 32 + nt * 8 + l2;
            float b0 = sBias[col], b1 = sBias[col + 1];
            sC[col * 257 + row]            = acc[mt][nt][0] + b0;
            sC[(col + 1) * 257 + row]      = acc[mt][nt][1] + b1;
            sC[col * 257 + row + 8]        = acc[mt][nt][2] + b0;
            sC[(col + 1) * 257 + row + 8]  = acc[mt][nt][3] + b1;
        }
    __syncthreads();
    // coalesced store: iter k covers one oc row of 256 pixels
    for (int i = tid; i < 64 * 256; i += 256) {
        int oc = i >> 8, m = i & 255;
        int pr = m >> 5, pc = m & 31;
        out[((size_t)(n * 64 + oc) * H + brow + pr) * W + bcol + pc] = sC[oc * 257 + m];
    }
    // BN stats: thread t<64 owns oc=t; stride-257 => bank (oc+m)%32, conflict-free
    if (tid < 64) {
        int oc = tid;
        float s = 0.0f;
        float q = 0.0f;
        const float* row = sC + oc * 257;
        #pragma unroll 8
        for (int m = 0; m < 256; m++) {
            float x = row[m];
            s += x; q = fmaf(x, x, q);
        }
        atomicAdd(&g_sum[ostage][oc], (double)s);
        atomicAdd(&g_sq [ostage][oc], (double)q);
    }
}

// ===================== elementwise / DWT kernels ===========================
__global__ void bnrelu_dwt_kernel(const float* __restrict__ x2,
                                  float* __restrict__ skip, float* __restrict__ dwt) {
    size_t i = (size_t)blockIdx.x * blockDim.x + threadIdx.x;
    if (i >= DWT_ELEMS) return;
    int x = (int)(i & 255), y = (int)((i >> 8) & 255);
    int c = (int)((i >> 16) & 63), n = (int)(i >> 22);
    const float sc = g_nsc[1][c], sh = g_nsh[1][c];
    const size_t base = ((size_t)(n * 64 + c) * 512 + 2 * y) * 512 + 2 * x;
    float2 r0 = *(const float2*)(x2 + base);
    float2 r1 = *(const float2*)(x2 + base + 512);
    float s00 = fmaxf(fmaf(r0.x, sc, sh), 0.0f);
    float s01 = fmaxf(fmaf(r0.y, sc, sh), 0.0f);
    float s10 = fmaxf(fmaf(r1.x, sc, sh), 0.0f);
    float s11 = fmaxf(fmaf(r1.y, sc, sh), 0.0f);
    *(float2*)(skip + base)       = make_float2(s00, s01);
    *(float2*)(skip + base + 512) = make_float2(s10, s11);
    size_t ob = ((size_t)(n * 256 + c)) * 65536 + (size_t)y * 256 + x;
    dwt[ob                 ] = 0.5f * (s00 + s01 + s10 + s11);
    dwt[ob +  64ull * 65536] = 0.5f * (s00 + s01 - s10 - s11);
    dwt[ob + 128ull * 65536] = 0.5f * (s00 - s01 + s10 - s11);
    dwt[ob + 192ull * 65536] = 0.5f * (s00 - s01 - s10 + s11);
}

__global__ void bnrelu4_kernel(float* __restrict__ buf) {
    size_t i4 = (size_t)blockIdx.x * blockDim.x + threadIdx.x;
    if (i4 >= (DWT_ELEMS >> 2)) return;
    int c = (int)((i4 >> 14) & 63);
    const float sc = g_nsc[2][c], sh = g_nsh[2][c];
    float4 v = ((float4*)buf)[i4];
    v.x = fmaxf(fmaf(v.x, sc, sh), 0.0f);
    v.y = fmaxf(fmaf(v.y, sc, sh), 0.0f);
    v.z = fmaxf(fmaf(v.z, sc, sh), 0.0f);
    v.w = fmaxf(fmaf(v.w, sc, sh), 0.0f);
    ((float4*)buf)[i4] = v;
}

// ================================ launch ===================================
extern "C" void kernel_launch(void* const* d_in, const int* in_sizes, int n_in,
                              void* d_out, int out_size) {
    const float* x   = (const float*)d_in[0];
    const float* w1  = (const float*)d_in[1];
    const float* b1  = (const float*)d_in[2];
    const float* g1  = (const float*)d_in[3];
    const float* be1 = (const float*)d_in[4];
    const float* w2  = (const float*)d_in[5];
    const float* b2  = (const float*)d_in[6];
    const float* g2  = (const float*)d_in[7];
    const float* be2 = (const float*)d_in[8];
    const float* w3  = (const float*)d_in[9];
    const float* b3  = (const float*)d_in[10];
    const float* g3  = (const float*)d_in[11];
    const float* be3 = (const float*)d_in[12];

    float* out      = (float*)d_out;
    float* dwt_out  = out;
    float* skip_con = out + DWT_ELEMS;

    float *bufA, *bufB, *wT;
    __nv_bfloat16* wB;
    cudaGetSymbolAddress((void**)&bufA, g_bufA);
    cudaGetSymbolAddress((void**)&bufB, g_bufB);
    cudaGetSymbolAddress((void**)&wT,   g_wT);
    cudaGetSymbolAddress((void**)&wB,   g_wB);

    cudaFuncSetAttribute(conv_mma_kernel<true>,
                         cudaFuncAttributeMaxDynamicSharedMemorySize, MM_SMEM);
    cudaFuncSetAttribute(conv_mma_kernel<false>,
                         cudaFuncAttributeMaxDynamicSharedMemorySize, MM_SMEM);

    const double inv_cnt_hi = 1.0 / (4.0 * 512.0 * 512.0);
    const double inv_cnt_lo = 1.0 / (4.0 * 256.0 * 256.0);

    zero_stats_kernel<<<1, 192>>>();

    // conv1 (FFMA, C=3) -> bufA, stats stage 0
    transpose_w_kernel<<<(3 * 576 + 255) / 256, 256>>>(w1, wT, 3);
    conv3x3_kernel<false><<<dim3(16, 64, 4), 512>>>(x, wT, b1, bufA, 3, 512, 512, 0, 0);
    finalize_stats_kernel<<<1, 64>>>(0, g1, be1, inv_cnt_hi);

    // conv2 (mma.sync, BN1 folded): bufA -> bufB, stats stage 1 in epilogue
    prep_wmma_kernel<<<(82944 + 255) / 256, 256>>>(w2, wB, 64);
    conv_mma_kernel<true><<<dim3(16, 64, 4), 256, MM_SMEM>>>(
        bufA, wB, b2, bufB, 64, 512, 512, 0, 1);
    finalize_stats_kernel<<<1, 64>>>(1, g2, be2, inv_cnt_hi);

    // fused BN2+ReLU+DWT: bufB -> skip_con + bufA(dwt)
    bnrelu_dwt_kernel<<<65536, 256>>>(bufB, skip_con, bufA);

    // conv3 (mma.sync): bufA(dwt, C=256) -> dwt_out (raw), stats stage 2
    prep_wmma_kernel<<<(331776 + 255) / 256, 256>>>(w3, wB, 256);
    conv_mma_kernel<false><<<dim3(8, 32, 4), 256, MM_SMEM>>>(
        bufA, wB, b3, dwt_out, 256, 256, 256, 0, 2);
    finalize_stats_kernel<<<1, 64>>>(2, g3, be3, inv_cnt_lo);

    // final BN3+ReLU in place
    bnrelu4_kernel<<<16384, 256>>>(dwt_out);
}